// round 1
// baseline (speedup 1.0000x reference)
#include <cuda_runtime.h>

#define HH   4
#define FF   32
#define HFD  128          // H*F
#define FIN  128
#define EDIM 64
#define HID  256
#define BB   64
#define MLE  1500
#define NN   (BB*MLE)     // 96000
#define EE   600000

// ---------------- scratch (device globals; no allocation allowed) ----------
__device__ float g_proj[NN*HFD];      // 49.2 MB
__device__ float g_ss[NN*HH];
__device__ float g_st[NN*HH];
__device__ float g_dt[NN*HH];         // denom for trg-aggregated branch
__device__ float g_ds[NN*HH];         // denom for src-aggregated branch
__device__ float g_s[EE*HH];          // scores, then exp(scores - M) in place
__device__ float g_usrc[BB*HFD];
__device__ float g_utrg[BB*HFD];
__device__ float g_v[BB*HH*EDIM];
__device__ unsigned g_max_ord;

// ---------------- helpers --------------------------------------------------
__device__ __forceinline__ unsigned f2ord(float f) {
    unsigned b = __float_as_uint(f);
    return (b & 0x80000000u) ? ~b : (b | 0x80000000u);
}
__device__ __forceinline__ float ord2f(unsigned u) {
    unsigned b = (u & 0x80000000u) ? (u & 0x7fffffffu) : ~u;
    return __uint_as_float(b);
}
__device__ __forceinline__ void red4(float* addr, float4 v) {
    asm volatile("red.global.add.v4.f32 [%0], {%1,%2,%3,%4};"
                 :: "l"(addr), "f"(v.x), "f"(v.y), "f"(v.z), "f"(v.w) : "memory");
}
__device__ __forceinline__ float lrelu(float x) { return x > 0.f ? x : 0.2f * x; }

// ---------------- K0z: zero denominators + init max ------------------------
__global__ void zero_kernel() {
    int i = blockIdx.x * 256 + threadIdx.x;
    if (i < NN * HH) { g_dt[i] = 0.f; g_ds[i] = 0.f; }
    if (i == 0) g_max_ord = 0x007FFFFFu;   // encodes -inf
}

// ---------------- K0: per-batch instruction bridges ------------------------
// u_src[b,hf] = a_src[hf]*(ins[b]@W_src+b_src)[hf]  (same for trg)
// v[b,h,d]    = sum_f W_edge[d, h*32+f] * a_edge*(ins[b]@W_edge_ins+b_edge)
__global__ void prep_kernel(const float* __restrict__ ins,
                            const float* __restrict__ Wsi, const float* __restrict__ bsi,
                            const float* __restrict__ Wti, const float* __restrict__ bti,
                            const float* __restrict__ Wei, const float* __restrict__ bei,
                            const float* __restrict__ asrc, const float* __restrict__ atrg,
                            const float* __restrict__ aedge, const float* __restrict__ Wedge) {
    __shared__ float si[HID];
    __shared__ float ce[HFD];
    int b = blockIdx.x, t = threadIdx.x;   // 128 threads
    for (int k = t; k < HID; k += 128) si[k] = ins[b * HID + k];
    __syncthreads();
    float s1 = bsi[t], s2 = bti[t], s3 = bei[t];
    for (int k = 0; k < HID; k++) {
        float iv = si[k];
        s1 += iv * Wsi[k * HFD + t];
        s2 += iv * Wti[k * HFD + t];
        s3 += iv * Wei[k * HFD + t];
    }
    g_usrc[b * HFD + t] = s1 * asrc[t];
    g_utrg[b * HFD + t] = s2 * atrg[t];
    ce[t] = s3 * aedge[t];
    __syncthreads();
    for (int o = t; o < HH * EDIM; o += 128) {
        int h = o >> 6, d = o & 63;
        float v = 0.f;
        #pragma unroll
        for (int f = 0; f < FF; f++) v += Wedge[d * HFD + h * FF + f] * ce[h * FF + f];
        g_v[b * HH * EDIM + o] = v;
    }
}

// ---------------- K1: fused node GEMM + scores + skip init -----------------
// out cols 0..127 -> proj (g_proj + smem), 128..255 -> skip (into both halves of d_out)
#define TILE_N 64
#define KCOLS  256
#define SMEM_BYTES ((FIN*KCOLS + TILE_N*129) * 4)

__global__ void node_kernel(const float* __restrict__ x,
                            const float* __restrict__ Wp,
                            const float* __restrict__ Wsk,
                            const float* __restrict__ bias,
                            float* __restrict__ out) {
    extern __shared__ float smem[];
    float* sW = smem;                 // [128][256]
    float* sX = smem + FIN * KCOLS;   // [64][129] padded (reused as proj tile)
    int tid = threadIdx.x;

    const float4* Wp4 = (const float4*)Wp;
    const float4* Ws4 = (const float4*)Wsk;
    for (int i4 = tid; i4 < FIN * KCOLS / 4; i4 += 256) {
        int k = i4 >> 6, c4 = i4 & 63;
        float4 v = (c4 < 32) ? Wp4[k * 32 + c4] : Ws4[k * 32 + (c4 - 32)];
        ((float4*)sW)[i4] = v;
    }
    int base = blockIdx.x * TILE_N;
    const float4* x4 = (const float4*)x;
    for (int i = tid; i < TILE_N * 32; i += 256) {
        int r = i >> 5, k4 = i & 31;
        float4 v = x4[(base + r) * 32 + k4];
        int s = r * 129 + k4 * 4;
        sX[s] = v.x; sX[s + 1] = v.y; sX[s + 2] = v.z; sX[s + 3] = v.w;
    }
    __syncthreads();

    int tcol = tid & 31, trow = tid >> 5;   // warp id = trow (rows), lanes = cols
    float acc[8][8];
    #pragma unroll
    for (int j = 0; j < 8; j++)
        #pragma unroll
        for (int i = 0; i < 8; i++) acc[j][i] = 0.f;

    for (int k = 0; k < FIN; k++) {
        float xr[8], wr[8];
        #pragma unroll
        for (int j = 0; j < 8; j++) xr[j] = sX[(trow * 8 + j) * 129 + k];  // broadcast
        #pragma unroll
        for (int i = 0; i < 8; i++) wr[i] = sW[k * KCOLS + tcol + 32 * i]; // conflict-free
        #pragma unroll
        for (int j = 0; j < 8; j++)
            #pragma unroll
            for (int i = 0; i < 8; i++) acc[j][i] = fmaf(xr[j], wr[i], acc[j][i]);
    }
    __syncthreads();   // everyone done reading sX before we overwrite it with proj

    #pragma unroll
    for (int j = 0; j < 8; j++) {
        int ln = trow * 8 + j;
        int gn = base + ln;
        #pragma unroll
        for (int i = 0; i < 8; i++) {
            int c = tcol + 32 * i;
            float v = acc[j][i];
            if (c < HFD) {
                g_proj[gn * HFD + c] = v;
                sX[ln * 129 + c] = v;                // proj tile for score phase
            } else {
                int oj = c - HFD;
                float o = v + bias[oj];              // skip + bias, both halves
                out[(size_t)gn * 256 + oj] = o;
                out[(size_t)gn * 256 + 128 + oj] = o;
            }
        }
    }
    __syncthreads();

    // scores: 256 threads = 64 nodes x 4 heads (warp => 32 nodes, fixed head)
    int ln = tid & 63, h = tid >> 6;
    int gn = base + ln;
    int b = gn / MLE;
    const float* us = g_usrc + b * HFD + h * FF;
    const float* ut = g_utrg + b * HFD + h * FF;
    const float* pr = sX + ln * 129 + h * FF;
    float a = 0.f, c2 = 0.f;
    #pragma unroll
    for (int f = 0; f < FF; f++) { float p = pr[f]; a = fmaf(p, us[f], a); c2 = fmaf(p, ut[f], c2); }
    g_ss[gn * HH + h] = a;
    g_st[gn * HH + h] = c2;
}

// ---------------- K2: per-edge scores + leaky relu + global max ------------
__global__ void escore_kernel(const int* __restrict__ eidx,
                              const float* __restrict__ edges,
                              const int* __restrict__ bids) {
    int e = blockIdx.x * 256 + threadIdx.x;
    float m = -3.4e38f;
    if (e < EE) {
        int b = bids[e];
        int src = eidx[e], trg = eidx[EE + e];
        const float4* er = (const float4*)edges + e * 16;
        const float4* vb = (const float4*)g_v + b * 64;
        float se0 = 0.f, se1 = 0.f, se2 = 0.f, se3 = 0.f;
        #pragma unroll
        for (int q = 0; q < 16; q++) {
            float4 ev = er[q];
            float4 v0 = vb[q], v1 = vb[16 + q], v2 = vb[32 + q], v3 = vb[48 + q];
            se0 += ev.x * v0.x + ev.y * v0.y + ev.z * v0.z + ev.w * v0.w;
            se1 += ev.x * v1.x + ev.y * v1.y + ev.z * v1.z + ev.w * v1.w;
            se2 += ev.x * v2.x + ev.y * v2.y + ev.z * v2.z + ev.w * v2.w;
            se3 += ev.x * v3.x + ev.y * v3.y + ev.z * v3.z + ev.w * v3.w;
        }
        float4 ss = ((const float4*)g_ss)[src];
        float4 st = ((const float4*)g_st)[trg];
        float s0 = lrelu(ss.x + st.x + se0);
        float s1 = lrelu(ss.y + st.y + se1);
        float s2 = lrelu(ss.z + st.z + se2);
        float s3 = lrelu(ss.w + st.w + se3);
        ((float4*)g_s)[e] = make_float4(s0, s1, s2, s3);
        m = fmaxf(fmaxf(s0, s1), fmaxf(s2, s3));
    }
    #pragma unroll
    for (int off = 16; off; off >>= 1) m = fmaxf(m, __shfl_xor_sync(0xffffffffu, m, off));
    __shared__ float wm[8];
    if ((threadIdx.x & 31) == 0) wm[threadIdx.x >> 5] = m;
    __syncthreads();
    if (threadIdx.x < 8) {
        m = wm[threadIdx.x];
        #pragma unroll
        for (int off = 4; off; off >>= 1) m = fmaxf(m, __shfl_xor_sync(0xffu, m, off));
        if (threadIdx.x == 0) atomicMax(&g_max_ord, f2ord(m));
    }
}

// ---------------- K3: exp + segment denominators ---------------------------
__global__ void denom_kernel(const int* __restrict__ eidx) {
    int e = blockIdx.x * 256 + threadIdx.x;
    if (e >= EE) return;
    float M = ord2f(g_max_ord);
    float4 s = ((const float4*)g_s)[e];
    float4 ex = make_float4(__expf(s.x - M), __expf(s.y - M),
                            __expf(s.z - M), __expf(s.w - M));
    ((float4*)g_s)[e] = ex;
    int src = eidx[e], trg = eidx[EE + e];
    red4(g_dt + trg * 4, ex);
    red4(g_ds + src * 4, ex);
}

// ---------------- K4: weighted aggregation (warp per edge) -----------------
// trg half (cols 128..255): out[trg] += proj[src]*e/(dt[trg]+eps)
// src half (cols 0..127)  : out[src] += proj[trg]*e/(ds[src]+eps)
__device__ __forceinline__ float comp4(float4 v, int h) {
    return h == 0 ? v.x : h == 1 ? v.y : h == 2 ? v.z : v.w;
}
__global__ void agg_kernel(const int* __restrict__ eidx, float* __restrict__ out) {
    int e = (blockIdx.x * 256 + threadIdx.x) >> 5;
    int lane = threadIdx.x & 31;
    if (e >= EE) return;
    int src = eidx[e], trg = eidx[EE + e];
    float4 ex = __ldg((const float4*)g_s + e);
    float4 dt = __ldg((const float4*)g_dt + trg);
    float4 ds = __ldg((const float4*)g_ds + src);
    int h = lane >> 3;
    float eh  = comp4(ex, h);
    float att_t = eh / (comp4(dt, h) + 1e-16f);
    float att_s = eh / (comp4(ds, h) + 1e-16f);
    float4 ps = __ldg((const float4*)g_proj + src * 32 + lane);
    float4 pt = __ldg((const float4*)g_proj + trg * 32 + lane);
    red4(out + (size_t)trg * 256 + 128 + lane * 4,
         make_float4(ps.x * att_t, ps.y * att_t, ps.z * att_t, ps.w * att_t));
    red4(out + (size_t)src * 256 + lane * 4,
         make_float4(pt.x * att_s, pt.y * att_s, pt.z * att_s, pt.w * att_s));
}

// ---------------- K5: LayerNorm over 256 (warp per node, two-pass) ---------
__global__ void ln_kernel(float* __restrict__ out,
                          const float* __restrict__ gamma,
                          const float* __restrict__ beta) {
    int node = blockIdx.x * 8 + (threadIdx.x >> 5);
    int lane = threadIdx.x & 31;
    float4* row = (float4*)(out + (size_t)node * 256);
    float4 a = row[lane];
    float4 b = row[32 + lane];
    float s = a.x + a.y + a.z + a.w + b.x + b.y + b.z + b.w;
    #pragma unroll
    for (int off = 16; off; off >>= 1) s += __shfl_xor_sync(0xffffffffu, s, off);
    float mu = s * (1.f / 256.f);
    float dx, sq = 0.f;
    dx = a.x - mu; sq += dx * dx;  dx = a.y - mu; sq += dx * dx;
    dx = a.z - mu; sq += dx * dx;  dx = a.w - mu; sq += dx * dx;
    dx = b.x - mu; sq += dx * dx;  dx = b.y - mu; sq += dx * dx;
    dx = b.z - mu; sq += dx * dx;  dx = b.w - mu; sq += dx * dx;
    #pragma unroll
    for (int off = 16; off; off >>= 1) sq += __shfl_xor_sync(0xffffffffu, sq, off);
    float inv = rsqrtf(sq * (1.f / 256.f) + 1e-5f);
    float4 g1 = ((const float4*)gamma)[lane], g2 = ((const float4*)gamma)[32 + lane];
    float4 b1 = ((const float4*)beta)[lane],  b2 = ((const float4*)beta)[32 + lane];
    a.x = (a.x - mu) * inv * g1.x + b1.x;  a.y = (a.y - mu) * inv * g1.y + b1.y;
    a.z = (a.z - mu) * inv * g1.z + b1.z;  a.w = (a.w - mu) * inv * g1.w + b1.w;
    b.x = (b.x - mu) * inv * g2.x + b2.x;  b.y = (b.y - mu) * inv * g2.y + b2.y;
    b.z = (b.z - mu) * inv * g2.z + b2.z;  b.w = (b.w - mu) * inv * g2.w + b2.w;
    row[lane] = a;
    row[32 + lane] = b;
}

// ---------------- launch ---------------------------------------------------
extern "C" void kernel_launch(void* const* d_in, const int* in_sizes, int n_in,
                              void* d_out, int out_size) {
    // slot 5 is the python-int max_local_entity (scalar). If the harness drops
    // scalar inputs, parameter slots shift down by one.
    int o = (in_sizes[5] == 1) ? 0 : -1;
    const float* x     = (const float*)d_in[0];
    const int*   eidx  = (const int*)  d_in[1];
    const float* edges = (const float*)d_in[2];
    const float* ins   = (const float*)d_in[3];
    const int*   bids  = (const int*)  d_in[4];
    const float* Wp    = (const float*)d_in[6 + o];
    const float* We    = (const float*)d_in[7 + o];
    const float* Wsi   = (const float*)d_in[8 + o];
    const float* bsi   = (const float*)d_in[9 + o];
    const float* Wti   = (const float*)d_in[10 + o];
    const float* bti   = (const float*)d_in[11 + o];
    const float* Wei   = (const float*)d_in[12 + o];
    const float* bei   = (const float*)d_in[13 + o];
    const float* asrc  = (const float*)d_in[14 + o];
    const float* atrg  = (const float*)d_in[15 + o];
    const float* aedge = (const float*)d_in[16 + o];
    const float* bias  = (const float*)d_in[17 + o];
    const float* Wsk   = (const float*)d_in[18 + o];
    const float* gam   = (const float*)d_in[19 + o];
    const float* bet   = (const float*)d_in[20 + o];
    float* out = (float*)d_out;

    cudaFuncSetAttribute(node_kernel, cudaFuncAttributeMaxDynamicSharedMemorySize, SMEM_BYTES);

    zero_kernel<<<(NN * HH + 255) / 256, 256>>>();
    prep_kernel<<<BB, 128>>>(ins, Wsi, bsi, Wti, bti, Wei, bei, asrc, atrg, aedge, We);
    node_kernel<<<NN / TILE_N, 256, SMEM_BYTES>>>(x, Wp, Wsk, bias, out);
    escore_kernel<<<(EE + 255) / 256, 256>>>(eidx, edges, bids);
    denom_kernel<<<(EE + 255) / 256, 256>>>(eidx);
    agg_kernel<<<EE / 8, 256>>>(eidx, out);
    ln_kernel<<<NN / 8, 256>>>(out, gam, bet);
}

// round 2
// speedup vs baseline: 1.1033x; 1.1033x over previous
#include <cuda_runtime.h>

#define HH   4
#define FF   32
#define HFD  128          // H*F
#define FIN  128
#define EDIM 64
#define HID  256
#define BB   64
#define MLE  1500
#define NN   (BB*MLE)     // 96000
#define EE   600000
#define CAP  64           // per-node incidence capacity (P(overflow) ~ 1e-50)

// ---------------- scratch (device globals; no allocation allowed) ----------
__device__ float g_proj[NN*HFD];      // 49.2 MB
__device__ float g_ss[NN*HH];
__device__ float g_st[NN*HH];
__device__ float g_s[EE*HH];          // scores, then exp(scores - M) in place
__device__ float g_usrc[BB*HFD];
__device__ float g_utrg[BB*HFD];
__device__ float g_v[BB*HH*EDIM];
__device__ unsigned g_max_ord;
__device__ int g_degt[NN];
__device__ int g_degs[NN];
__device__ int g_listt[NN*CAP];       // edges whose trg == n
__device__ int g_lists[NN*CAP];       // edges whose src == n

// ---------------- helpers --------------------------------------------------
__device__ __forceinline__ unsigned f2ord(float f) {
    unsigned b = __float_as_uint(f);
    return (b & 0x80000000u) ? ~b : (b | 0x80000000u);
}
__device__ __forceinline__ float ord2f(unsigned u) {
    unsigned b = (u & 0x80000000u) ? (u & 0x7fffffffu) : ~u;
    return __uint_as_float(b);
}
__device__ __forceinline__ float lrelu(float x) { return x > 0.f ? x : 0.2f * x; }
__device__ __forceinline__ float comp4(float4 v, int h) {
    return h == 0 ? v.x : h == 1 ? v.y : h == 2 ? v.z : v.w;
}
__device__ __forceinline__ float shfl_comp(float4 v, int src, int h) {
    float e0 = __shfl_sync(0xffffffffu, v.x, src);
    float e1 = __shfl_sync(0xffffffffu, v.y, src);
    float e2 = __shfl_sync(0xffffffffu, v.z, src);
    float e3 = __shfl_sync(0xffffffffu, v.w, src);
    return h == 0 ? e0 : (h == 1 ? e1 : (h == 2 ? e2 : e3));
}

// ---------------- K0z: zero degree counters + init max ---------------------
__global__ void zero_kernel() {
    int i = blockIdx.x * 256 + threadIdx.x;
    if (i < NN) { g_degt[i] = 0; g_degs[i] = 0; }
    if (i == 0) g_max_ord = 0x007FFFFFu;   // encodes -inf
}

// ---------------- K0: per-batch instruction bridges ------------------------
__global__ void prep_kernel(const float* __restrict__ ins,
                            const float* __restrict__ Wsi, const float* __restrict__ bsi,
                            const float* __restrict__ Wti, const float* __restrict__ bti,
                            const float* __restrict__ Wei, const float* __restrict__ bei,
                            const float* __restrict__ asrc, const float* __restrict__ atrg,
                            const float* __restrict__ aedge, const float* __restrict__ Wedge) {
    __shared__ float si[HID];
    __shared__ float ce[HFD];
    int b = blockIdx.x, t = threadIdx.x;   // 128 threads
    for (int k = t; k < HID; k += 128) si[k] = ins[b * HID + k];
    __syncthreads();
    float s1 = bsi[t], s2 = bti[t], s3 = bei[t];
    for (int k = 0; k < HID; k++) {
        float iv = si[k];
        s1 += iv * Wsi[k * HFD + t];
        s2 += iv * Wti[k * HFD + t];
        s3 += iv * Wei[k * HFD + t];
    }
    g_usrc[b * HFD + t] = s1 * asrc[t];
    g_utrg[b * HFD + t] = s2 * atrg[t];
    ce[t] = s3 * aedge[t];
    __syncthreads();
    for (int o = t; o < HH * EDIM; o += 128) {
        int h = o >> 6, d = o & 63;
        float v = 0.f;
        #pragma unroll
        for (int f = 0; f < FF; f++) v += Wedge[d * HFD + h * FF + f] * ce[h * FF + f];
        g_v[b * HH * EDIM + o] = v;
    }
}

// ---------------- K1: fused node GEMM + scores + skip init -----------------
#define TILE_N 64
#define KCOLS  256
#define SMEM_BYTES ((FIN*KCOLS + TILE_N*129) * 4)

__global__ void node_kernel(const float* __restrict__ x,
                            const float* __restrict__ Wp,
                            const float* __restrict__ Wsk,
                            const float* __restrict__ bias,
                            float* __restrict__ out) {
    extern __shared__ float smem[];
    float* sW = smem;                 // [128][256]
    float* sX = smem + FIN * KCOLS;   // [64][129] padded (reused as proj tile)
    int tid = threadIdx.x;

    const float4* Wp4 = (const float4*)Wp;
    const float4* Ws4 = (const float4*)Wsk;
    for (int i4 = tid; i4 < FIN * KCOLS / 4; i4 += 256) {
        int k = i4 >> 6, c4 = i4 & 63;
        float4 v = (c4 < 32) ? Wp4[k * 32 + c4] : Ws4[k * 32 + (c4 - 32)];
        ((float4*)sW)[i4] = v;
    }
    int base = blockIdx.x * TILE_N;
    const float4* x4 = (const float4*)x;
    for (int i = tid; i < TILE_N * 32; i += 256) {
        int r = i >> 5, k4 = i & 31;
        float4 v = x4[(base + r) * 32 + k4];
        int s = r * 129 + k4 * 4;
        sX[s] = v.x; sX[s + 1] = v.y; sX[s + 2] = v.z; sX[s + 3] = v.w;
    }
    __syncthreads();

    int tcol = tid & 31, trow = tid >> 5;
    float acc[8][8];
    #pragma unroll
    for (int j = 0; j < 8; j++)
        #pragma unroll
        for (int i = 0; i < 8; i++) acc[j][i] = 0.f;

    for (int k = 0; k < FIN; k++) {
        float xr[8], wr[8];
        #pragma unroll
        for (int j = 0; j < 8; j++) xr[j] = sX[(trow * 8 + j) * 129 + k];
        #pragma unroll
        for (int i = 0; i < 8; i++) wr[i] = sW[k * KCOLS + tcol + 32 * i];
        #pragma unroll
        for (int j = 0; j < 8; j++)
            #pragma unroll
            for (int i = 0; i < 8; i++) acc[j][i] = fmaf(xr[j], wr[i], acc[j][i]);
    }
    __syncthreads();

    #pragma unroll
    for (int j = 0; j < 8; j++) {
        int ln = trow * 8 + j;
        int gn = base + ln;
        #pragma unroll
        for (int i = 0; i < 8; i++) {
            int c = tcol + 32 * i;
            float v = acc[j][i];
            if (c < HFD) {
                g_proj[gn * HFD + c] = v;
                sX[ln * 129 + c] = v;
            } else {
                int oj = c - HFD;
                float o = v + bias[oj];
                out[(size_t)gn * 256 + oj] = o;
                out[(size_t)gn * 256 + 128 + oj] = o;
            }
        }
    }
    __syncthreads();

    int ln = tid & 63, h = tid >> 6;
    int gn = base + ln;
    int b = gn / MLE;
    const float* us = g_usrc + b * HFD + h * FF;
    const float* ut = g_utrg + b * HFD + h * FF;
    const float* pr = sX + ln * 129 + h * FF;
    float a = 0.f, c2 = 0.f;
    #pragma unroll
    for (int f = 0; f < FF; f++) { float p = pr[f]; a = fmaf(p, us[f], a); c2 = fmaf(p, ut[f], c2); }
    g_ss[gn * HH + h] = a;
    g_st[gn * HH + h] = c2;
}

// ---------------- K2: per-edge scores, v staged in SMEM --------------------
// sv padded: float4 index = b*65 + h*16 + q  -> bank phase (b+q)%8 spreads
#define SV_F4 (BB*65)
#define ESC_SMEM (SV_F4*16)

__global__ void escore_kernel(const int* __restrict__ eidx,
                              const float* __restrict__ edges,
                              const int* __restrict__ bids) {
    extern __shared__ float4 sv[];
    const float4* v4 = (const float4*)g_v;
    for (int i = threadIdx.x; i < BB * 64; i += 256) {
        int b = i >> 6, r = i & 63;
        sv[b * 65 + r] = v4[i];
    }
    __syncthreads();

    float m = -3.4e38f;
    for (int e = blockIdx.x * 256 + threadIdx.x; e < EE; e += gridDim.x * 256) {
        int b = bids[e];
        int src = eidx[e], trg = eidx[EE + e];
        const float4* er = (const float4*)edges + e * 16;
        const float4* vb = sv + b * 65;
        float se0 = 0.f, se1 = 0.f, se2 = 0.f, se3 = 0.f;
        #pragma unroll
        for (int q = 0; q < 16; q++) {
            float4 ev = er[q];
            float4 v0 = vb[q], v1 = vb[16 + q], v2 = vb[32 + q], v3 = vb[48 + q];
            se0 += ev.x * v0.x + ev.y * v0.y + ev.z * v0.z + ev.w * v0.w;
            se1 += ev.x * v1.x + ev.y * v1.y + ev.z * v1.z + ev.w * v1.w;
            se2 += ev.x * v2.x + ev.y * v2.y + ev.z * v2.z + ev.w * v2.w;
            se3 += ev.x * v3.x + ev.y * v3.y + ev.z * v3.z + ev.w * v3.w;
        }
        float4 ss = ((const float4*)g_ss)[src];
        float4 st = ((const float4*)g_st)[trg];
        float s0 = lrelu(ss.x + st.x + se0);
        float s1 = lrelu(ss.y + st.y + se1);
        float s2 = lrelu(ss.z + st.z + se2);
        float s3 = lrelu(ss.w + st.w + se3);
        ((float4*)g_s)[e] = make_float4(s0, s1, s2, s3);
        m = fmaxf(m, fmaxf(fmaxf(s0, s1), fmaxf(s2, s3)));
    }
    #pragma unroll
    for (int off = 16; off; off >>= 1) m = fmaxf(m, __shfl_xor_sync(0xffffffffu, m, off));
    __shared__ float wm[8];
    if ((threadIdx.x & 31) == 0) wm[threadIdx.x >> 5] = m;
    __syncthreads();
    if (threadIdx.x < 8) {
        m = wm[threadIdx.x];
        #pragma unroll
        for (int off = 4; off; off >>= 1) m = fmaxf(m, __shfl_xor_sync(0xffu, m, off));
        if (threadIdx.x == 0) atomicMax(&g_max_ord, f2ord(m));
    }
}

// ---------------- K3: exp in place + build incidence lists -----------------
__global__ void fill_kernel(const int* __restrict__ eidx) {
    int e = blockIdx.x * 256 + threadIdx.x;
    if (e >= EE) return;
    float M = ord2f(g_max_ord);
    float4 s = ((const float4*)g_s)[e];
    float4 ex = make_float4(__expf(s.x - M), __expf(s.y - M),
                            __expf(s.z - M), __expf(s.w - M));
    ((float4*)g_s)[e] = ex;
    int src = eidx[e], trg = eidx[EE + e];
    int pt = atomicAdd(&g_degt[trg], 1);
    if (pt < CAP) g_listt[trg * CAP + pt] = e;
    int ps = atomicAdd(&g_degs[src], 1);
    if (ps < CAP) g_lists[src * CAP + ps] = e;
}

// ---------------- K4: gather aggregation + denom + skip + LayerNorm --------
// warp per node; lane owns cols [4*lane, 4*lane+4) of each 128-wide half.
__global__ void gather_kernel(const int* __restrict__ eidx,
                              const float* __restrict__ gamma,
                              const float* __restrict__ beta,
                              float* __restrict__ out) {
    int n = blockIdx.x * 8 + (threadIdx.x >> 5);
    int lane = threadIdx.x & 31;
    int dt = g_degt[n]; if (dt > CAP) dt = CAP;
    int ds = g_degs[n]; if (ds > CAP) ds = CAP;
    const float4* ex4 = (const float4*)g_s;
    const float4* pr4 = (const float4*)g_proj;

    int nbt = 0, nbs = 0;
    float4 xt = make_float4(0.f, 0.f, 0.f, 0.f);
    float4 xs = make_float4(0.f, 0.f, 0.f, 0.f);
    if (lane < dt) { int e = g_listt[n * CAP + lane]; nbt = __ldg(eidx + e);      xt = __ldg(ex4 + e); }
    if (lane < ds) { int e = g_lists[n * CAP + lane]; nbs = __ldg(eidx + EE + e); xs = __ldg(ex4 + e); }

    // denominators (tail > 32 handled strided before reduce)
    float4 dT = xt, dS = xs;
    for (int i = 32 + lane; i < dt; i += 32) {
        float4 x = ex4[g_listt[n * CAP + i]];
        dT.x += x.x; dT.y += x.y; dT.z += x.z; dT.w += x.w;
    }
    for (int i = 32 + lane; i < ds; i += 32) {
        float4 x = ex4[g_lists[n * CAP + i]];
        dS.x += x.x; dS.y += x.y; dS.z += x.z; dS.w += x.w;
    }
    #pragma unroll
    for (int off = 16; off; off >>= 1) {
        dT.x += __shfl_xor_sync(0xffffffffu, dT.x, off);
        dT.y += __shfl_xor_sync(0xffffffffu, dT.y, off);
        dT.z += __shfl_xor_sync(0xffffffffu, dT.z, off);
        dT.w += __shfl_xor_sync(0xffffffffu, dT.w, off);
        dS.x += __shfl_xor_sync(0xffffffffu, dS.x, off);
        dS.y += __shfl_xor_sync(0xffffffffu, dS.y, off);
        dS.z += __shfl_xor_sync(0xffffffffu, dS.z, off);
        dS.w += __shfl_xor_sync(0xffffffffu, dS.w, off);
    }

    int h = lane >> 3;
    float4 aT = make_float4(0.f, 0.f, 0.f, 0.f);
    float4 aS = make_float4(0.f, 0.f, 0.f, 0.f);
    int mt = dt < 32 ? dt : 32;
    for (int i = 0; i < mt; i++) {
        int nbr = __shfl_sync(0xffffffffu, nbt, i);
        float a = shfl_comp(xt, i, h);
        float4 p = __ldg(pr4 + nbr * 32 + lane);
        aT.x += p.x * a; aT.y += p.y * a; aT.z += p.z * a; aT.w += p.w * a;
    }
    for (int i = 32; i < dt; i++) {              // essentially never taken
        int e = g_listt[n * CAP + i];
        float a = comp4(ex4[e], h);
        int nbr = eidx[e];
        float4 p = pr4[nbr * 32 + lane];
        aT.x += p.x * a; aT.y += p.y * a; aT.z += p.z * a; aT.w += p.w * a;
    }
    int ms = ds < 32 ? ds : 32;
    for (int i = 0; i < ms; i++) {
        int nbr = __shfl_sync(0xffffffffu, nbs, i);
        float a = shfl_comp(xs, i, h);
        float4 p = __ldg(pr4 + nbr * 32 + lane);
        aS.x += p.x * a; aS.y += p.y * a; aS.z += p.z * a; aS.w += p.w * a;
    }
    for (int i = 32; i < ds; i++) {
        int e = g_lists[n * CAP + i];
        float a = comp4(ex4[e], h);
        int nbr = eidx[EE + e];
        float4 p = pr4[nbr * 32 + lane];
        aS.x += p.x * a; aS.y += p.y * a; aS.z += p.z * a; aS.w += p.w * a;
    }

    float rT = 1.f / (comp4(dT, h) + 1e-16f);
    float rS = 1.f / (comp4(dS, h) + 1e-16f);

    float4* row = (float4*)(out + (size_t)n * 256);
    float4 v1 = row[lane];        // skip+bias (src half)
    float4 v2 = row[32 + lane];   // skip+bias (trg half)
    v1.x += aS.x * rS; v1.y += aS.y * rS; v1.z += aS.z * rS; v1.w += aS.w * rS;
    v2.x += aT.x * rT; v2.y += aT.y * rT; v2.z += aT.z * rT; v2.w += aT.w * rT;

    // LayerNorm over 256 within the warp
    float s = v1.x + v1.y + v1.z + v1.w + v2.x + v2.y + v2.z + v2.w;
    #pragma unroll
    for (int off = 16; off; off >>= 1) s += __shfl_xor_sync(0xffffffffu, s, off);
    float mu = s * (1.f / 256.f);
    float dx, sq = 0.f;
    dx = v1.x - mu; sq += dx * dx;  dx = v1.y - mu; sq += dx * dx;
    dx = v1.z - mu; sq += dx * dx;  dx = v1.w - mu; sq += dx * dx;
    dx = v2.x - mu; sq += dx * dx;  dx = v2.y - mu; sq += dx * dx;
    dx = v2.z - mu; sq += dx * dx;  dx = v2.w - mu; sq += dx * dx;
    #pragma unroll
    for (int off = 16; off; off >>= 1) sq += __shfl_xor_sync(0xffffffffu, sq, off);
    float inv = rsqrtf(sq * (1.f / 256.f) + 1e-5f);
    float4 g1 = ((const float4*)gamma)[lane], g2 = ((const float4*)gamma)[32 + lane];
    float4 b1 = ((const float4*)beta)[lane],  b2 = ((const float4*)beta)[32 + lane];
    v1.x = (v1.x - mu) * inv * g1.x + b1.x;  v1.y = (v1.y - mu) * inv * g1.y + b1.y;
    v1.z = (v1.z - mu) * inv * g1.z + b1.z;  v1.w = (v1.w - mu) * inv * g1.w + b1.w;
    v2.x = (v2.x - mu) * inv * g2.x + b2.x;  v2.y = (v2.y - mu) * inv * g2.y + b2.y;
    v2.z = (v2.z - mu) * inv * g2.z + b2.z;  v2.w = (v2.w - mu) * inv * g2.w + b2.w;
    row[lane] = v1;
    row[32 + lane] = v2;
}

// ---------------- launch ---------------------------------------------------
extern "C" void kernel_launch(void* const* d_in, const int* in_sizes, int n_in,
                              void* d_out, int out_size) {
    int o = (in_sizes[5] == 1) ? 0 : -1;
    const float* x     = (const float*)d_in[0];
    const int*   eidx  = (const int*)  d_in[1];
    const float* edges = (const float*)d_in[2];
    const float* ins   = (const float*)d_in[3];
    const int*   bids  = (const int*)  d_in[4];
    const float* Wp    = (const float*)d_in[6 + o];
    const float* We    = (const float*)d_in[7 + o];
    const float* Wsi   = (const float*)d_in[8 + o];
    const float* bsi   = (const float*)d_in[9 + o];
    const float* Wti   = (const float*)d_in[10 + o];
    const float* bti   = (const float*)d_in[11 + o];
    const float* Wei   = (const float*)d_in[12 + o];
    const float* bei   = (const float*)d_in[13 + o];
    const float* asrc  = (const float*)d_in[14 + o];
    const float* atrg  = (const float*)d_in[15 + o];
    const float* aedge = (const float*)d_in[16 + o];
    const float* bias  = (const float*)d_in[17 + o];
    const float* Wsk   = (const float*)d_in[18 + o];
    const float* gam   = (const float*)d_in[19 + o];
    const float* bet   = (const float*)d_in[20 + o];
    float* out = (float*)d_out;

    cudaFuncSetAttribute(node_kernel, cudaFuncAttributeMaxDynamicSharedMemorySize, SMEM_BYTES);
    cudaFuncSetAttribute(escore_kernel, cudaFuncAttributeMaxDynamicSharedMemorySize, ESC_SMEM);

    zero_kernel<<<(NN + 255) / 256, 256>>>();
    prep_kernel<<<BB, 128>>>(ins, Wsi, bsi, Wti, bti, Wei, bei, asrc, atrg, aedge, We);
    node_kernel<<<NN / TILE_N, 256, SMEM_BYTES>>>(x, Wp, Wsk, bias, out);
    escore_kernel<<<296, 256, ESC_SMEM>>>(eidx, edges, bids);
    fill_kernel<<<(EE + 255) / 256, 256>>>(eidx);
    gather_kernel<<<NN / 8, 256>>>(eidx, gam, bet, out);
}